// round 3
// baseline (speedup 1.0000x reference)
#include <cuda_runtime.h>
#include <cuda_bf16.h>
#include <cstdint>

// Problem constants (fixed by the reference).
#define N_TOTAL 1000000
#define N0      495616
#define N1      45056
#define N2      4096
#define E0      450560
#define E1      40960
#define D       128
#define PP      4096

// ---------------- device scratch (static, no runtime allocation) ----------------
__device__ float g_hn0[(size_t)N1 * D];   // layer0 neighbor mean
__device__ float g_h1 [(size_t)N1 * D];   // layer0 output (relu'd)
__device__ float g_hn1[(size_t)N2 * D];   // layer1 neighbor mean
__device__ float g_h2 [(size_t)N2 * D];   // layer1 output

__device__ int g_deg0[N1];
__device__ int g_off0[N1 + 1];
__device__ int g_cur0[N1];
__device__ int g_srcs0[E0];

__device__ int g_deg1[N2];
__device__ int g_off1[N2 + 1];
__device__ int g_cur1[N2];
__device__ int g_srcs1[E1];

// ---------------- small kernels: CSR build ----------------

__global__ void k_zero_deg() {
    int i = blockIdx.x * blockDim.x + threadIdx.x;
    if (i < N1) g_deg0[i] = 0;
    if (i < N2) g_deg1[i] = 0;
}

__global__ void k_count(const int* __restrict__ d0, const int* __restrict__ d1) {
    int i = blockIdx.x * blockDim.x + threadIdx.x;
    if (i < E0) atomicAdd(&g_deg0[d0[i]], 1);
    if (i < E1) atomicAdd(&g_deg1[d1[i]], 1);
}

// single-block exclusive scan (n <= ~64K), writes off[0..n] and cur[0..n-1]
__global__ void k_scan(const int* __restrict__ deg, int* __restrict__ off,
                       int* __restrict__ cur, int n) {
    __shared__ int wsum[32];
    __shared__ int s_carry;
    int tid = threadIdx.x, lane = tid & 31, wid = tid >> 5;
    if (tid == 0) s_carry = 0;
    __syncthreads();
    for (int base = 0; base < n; base += 1024) {
        int i = base + tid;
        int v = (i < n) ? deg[i] : 0;
        int x = v;
        #pragma unroll
        for (int o = 1; o < 32; o <<= 1) {
            int t = __shfl_up_sync(0xffffffffu, x, o);
            if (lane >= o) x += t;
        }
        if (lane == 31) wsum[wid] = x;
        __syncthreads();
        if (wid == 0) {
            int y = wsum[lane];
            #pragma unroll
            for (int o = 1; o < 32; o <<= 1) {
                int t = __shfl_up_sync(0xffffffffu, y, o);
                if (lane >= o) y += t;
            }
            wsum[lane] = y;
        }
        __syncthreads();
        int incl = x + (wid > 0 ? wsum[wid - 1] : 0);
        int c = s_carry;
        if (i < n) { int ex = c + incl - v; off[i] = ex; cur[i] = ex; }
        __syncthreads();                       // everyone read s_carry
        if (tid == 1023) s_carry = c + wsum[31];
        __syncthreads();
    }
    if (threadIdx.x == 0) off[n] = s_carry;
}

__global__ void k_scatter(const int* __restrict__ esrc, const int* __restrict__ edst,
                          int* __restrict__ cur, int* __restrict__ srcs, int E) {
    int e = blockIdx.x * blockDim.x + threadIdx.x;
    if (e < E) {
        int d = edst[e];
        int p = atomicAdd(&cur[d], 1);
        srcs[p] = esrc[e];
    }
}

// ---------------- neighbor-mean aggregation: one warp per dst ----------------

template <bool GATHER>
__global__ void k_aggregate(const float* __restrict__ feat, const int* __restrict__ nmap,
                            const int* __restrict__ srcs, const int* __restrict__ off,
                            float* __restrict__ outm, int ndst) {
    int w = (blockIdx.x * blockDim.x + threadIdx.x) >> 5;
    int lane = threadIdx.x & 31;
    if (w >= ndst) return;
    int s = off[w], e = off[w + 1];
    float4 acc = make_float4(0.f, 0.f, 0.f, 0.f);

    // index chain is dependent; software prefetch one edge ahead
    int nid_next = 0;
    if (s < e) {
        int src = __ldg(&srcs[s]);
        nid_next = GATHER ? __ldg(&nmap[src]) : src;
    }
    for (int t = s; t < e; t++) {
        int nid = nid_next;
        if (t + 1 < e) {
            int src = __ldg(&srcs[t + 1]);
            nid_next = GATHER ? __ldg(&nmap[src]) : src;
        }
        float4 v = ((const float4*)(feat + (size_t)nid * D))[lane];
        acc.x += v.x; acc.y += v.y; acc.z += v.z; acc.w += v.w;
    }
    float inv = 1.0f / fmaxf((float)(e - s), 1.0f);
    float4 o = make_float4(acc.x * inv, acc.y * inv, acc.z * inv, acc.w * inv);
    ((float4*)(outm + (size_t)w * D))[lane] = o;
}

// ---------------- fused SAGE GEMM: out = hd@Ws + hn@Wn + b (opt relu) ----------

__device__ __forceinline__ void fma4(float acc[4], float4 h,
                                     float4 w0, float4 w1, float4 w2, float4 w3) {
    acc[0] += h.x * w0.x + h.y * w1.x + h.z * w2.x + h.w * w3.x;
    acc[1] += h.x * w0.y + h.y * w1.y + h.z * w2.y + h.w * w3.y;
    acc[2] += h.x * w0.z + h.y * w1.z + h.z * w2.z + h.w * w3.z;
    acc[3] += h.x * w0.w + h.y * w1.w + h.z * w2.w + h.w * w3.w;
}

// smem: Ws[128x128] + Wn[128x128] + hd[32x128] + hn[32x128] = 160 KB
#define GEMM_SMEM_FLOATS (16384 + 16384 + 4096 + 4096)

template <bool RELU, bool GATHER>
__global__ void __launch_bounds__(256, 1)
k_gemm(const float* __restrict__ hsrc, const int* __restrict__ gidx,
       const float* __restrict__ hnei,
       const float* __restrict__ Ws, const float* __restrict__ Wn,
       const float* __restrict__ bias, float* __restrict__ out, int nrows) {
    extern __shared__ float smem[];
    float4* sWs = (float4*)smem;                       // 4096 float4
    float4* sWn = (float4*)(smem + 16384);             // 4096 float4
    float4* sHd = (float4*)(smem + 32768);             // 1024 float4
    float4* sHn = (float4*)(smem + 32768 + 4096);      // 1024 float4
    int tid = threadIdx.x;

    // stage both weight matrices once per block
    const float4* Ws4 = (const float4*)Ws;
    const float4* Wn4 = (const float4*)Wn;
    #pragma unroll 4
    for (int i = tid; i < 4096; i += 256) { sWs[i] = Ws4[i]; sWn[i] = Wn4[i]; }

    int cx = tid & 31;   // column quad: cols 4*cx .. 4*cx+3
    int ry = tid >> 5;   // row group:   rows 4*ry .. 4*ry+3 within tile
    int r0 = ry * 4;
    float4 bb = ((const float4*)bias)[cx];

    int ntiles = (nrows + 31) / 32;
    for (int tile = blockIdx.x; tile < ntiles; tile += gridDim.x) {
        int base = tile * 32;
        __syncthreads();   // previous compute done before overwriting h tiles
        // cooperative load of 32-row hd/hn tiles
        #pragma unroll
        for (int i = tid; i < 1024; i += 256) {
            int r = i >> 5, q = i & 31;
            int row = base + r;
            float4 vd = make_float4(0.f, 0.f, 0.f, 0.f);
            float4 vn = vd;
            if (row < nrows) {
                int nid = GATHER ? __ldg(&gidx[row]) : row;
                vd = ((const float4*)(hsrc + (size_t)nid * D))[q];
                vn = ((const float4*)(hnei + (size_t)row * D))[q];
            }
            sHd[i] = vd; sHn[i] = vn;
        }
        __syncthreads();

        float acc[4][4];
        #pragma unroll
        for (int r = 0; r < 4; r++) {
            acc[r][0] = bb.x; acc[r][1] = bb.y; acc[r][2] = bb.z; acc[r][3] = bb.w;
        }

        #pragma unroll 4
        for (int k4 = 0; k4 < 32; k4++) {
            int kb = 4 * k4;
            float4 ws0 = sWs[(kb + 0) * 32 + cx];
            float4 ws1 = sWs[(kb + 1) * 32 + cx];
            float4 ws2 = sWs[(kb + 2) * 32 + cx];
            float4 ws3 = sWs[(kb + 3) * 32 + cx];
            float4 wn0 = sWn[(kb + 0) * 32 + cx];
            float4 wn1 = sWn[(kb + 1) * 32 + cx];
            float4 wn2 = sWn[(kb + 2) * 32 + cx];
            float4 wn3 = sWn[(kb + 3) * 32 + cx];
            #pragma unroll
            for (int r = 0; r < 4; r++) {
                float4 hd = sHd[(r0 + r) * 32 + k4];   // warp-uniform: LDS broadcast
                float4 hn = sHn[(r0 + r) * 32 + k4];
                fma4(acc[r], hd, ws0, ws1, ws2, ws3);
                fma4(acc[r], hn, wn0, wn1, wn2, wn3);
            }
        }

        #pragma unroll
        for (int r = 0; r < 4; r++) {
            int row = base + r0 + r;
            if (row < nrows) {
                float4 o;
                if (RELU) {
                    o.x = fmaxf(acc[r][0], 0.f); o.y = fmaxf(acc[r][1], 0.f);
                    o.z = fmaxf(acc[r][2], 0.f); o.w = fmaxf(acc[r][3], 0.f);
                } else {
                    o.x = acc[r][0]; o.y = acc[r][1]; o.z = acc[r][2]; o.w = acc[r][3];
                }
                ((float4*)(out + (size_t)row * D))[cx] = o;
            }
        }
    }
}

// ---------------- final pos/neg gathers ----------------

__global__ void k_out(const int* __restrict__ ps, const int* __restrict__ pd,
                      const int* __restrict__ ns, const int* __restrict__ nd,
                      float* __restrict__ out) {
    int i = blockIdx.x * blockDim.x + threadIdx.x;   // 4*PP*32 float4 units
    if (i >= 4 * PP * 32) return;
    int q = i & 31;
    int row = i >> 5;
    int sec = row >> 12;           // PP == 4096
    int p = row & (PP - 1);
    const int* idx = (sec == 0) ? ps : (sec == 1) ? pd : (sec == 2) ? ns : nd;
    int h = __ldg(&idx[p]);
    ((float4*)out)[i] = ((const float4*)g_h2)[(size_t)h * 32 + q];
}

// ---------------- host launcher ----------------

extern "C" void kernel_launch(void* const* d_in, const int* in_sizes, int n_in,
                              void* d_out, int out_size) {
    const float* node_features = (const float*)d_in[0];
    const int*   input_nodes   = (const int*)d_in[1];
    const int*   e_src0        = (const int*)d_in[2];
    const int*   e_dst0        = (const int*)d_in[3];
    const int*   e_src1        = (const int*)d_in[4];
    const int*   e_dst1        = (const int*)d_in[5];
    const int*   pos_s         = (const int*)d_in[6];
    const int*   pos_d         = (const int*)d_in[7];
    const int*   neg_s         = (const int*)d_in[8];
    const int*   neg_d         = (const int*)d_in[9];
    const float* Ws0           = (const float*)d_in[10];
    const float* Wn0           = (const float*)d_in[11];
    const float* b0            = (const float*)d_in[12];
    const float* Ws1           = (const float*)d_in[13];
    const float* Wn1           = (const float*)d_in[14];
    const float* b1            = (const float*)d_in[15];
    float* out = (float*)d_out;

    // resolve device-global scratch addresses (no allocation)
    void *p_hn0, *p_h1, *p_hn1, *p_h2;
    void *p_deg0, *p_off0, *p_cur0, *p_srcs0;
    void *p_deg1, *p_off1, *p_cur1, *p_srcs1;
    cudaGetSymbolAddress(&p_hn0, g_hn0);
    cudaGetSymbolAddress(&p_h1,  g_h1);
    cudaGetSymbolAddress(&p_hn1, g_hn1);
    cudaGetSymbolAddress(&p_h2,  g_h2);
    cudaGetSymbolAddress(&p_deg0, g_deg0);
    cudaGetSymbolAddress(&p_off0, g_off0);
    cudaGetSymbolAddress(&p_cur0, g_cur0);
    cudaGetSymbolAddress(&p_srcs0, g_srcs0);
    cudaGetSymbolAddress(&p_deg1, g_deg1);
    cudaGetSymbolAddress(&p_off1, g_off1);
    cudaGetSymbolAddress(&p_cur1, g_cur1);
    cudaGetSymbolAddress(&p_srcs1, g_srcs1);

    float* hn0 = (float*)p_hn0;  float* h1 = (float*)p_h1;
    float* hn1 = (float*)p_hn1;  float* h2 = (float*)p_h2;
    int* deg0 = (int*)p_deg0; int* off0 = (int*)p_off0; int* cur0 = (int*)p_cur0; int* srcs0 = (int*)p_srcs0;
    int* deg1 = (int*)p_deg1; int* off1 = (int*)p_off1; int* cur1 = (int*)p_cur1; int* srcs1 = (int*)p_srcs1;

    const int smem_bytes = GEMM_SMEM_FLOATS * (int)sizeof(float);  // 163840
    cudaFuncSetAttribute((const void*)k_gemm<true, true>,
                         cudaFuncAttributeMaxDynamicSharedMemorySize, smem_bytes);
    cudaFuncSetAttribute((const void*)k_gemm<false, false>,
                         cudaFuncAttributeMaxDynamicSharedMemorySize, smem_bytes);

    // 1) CSR build for both layers
    k_zero_deg<<<(N1 + 255) / 256, 256>>>();
    k_count<<<(E0 + 255) / 256, 256>>>(e_dst0, e_dst1);
    k_scan<<<1, 1024>>>(deg0, off0, cur0, N1);
    k_scan<<<1, 1024>>>(deg1, off1, cur1, N2);
    k_scatter<<<(E0 + 255) / 256, 256>>>(e_src0, e_dst0, cur0, srcs0, E0);
    k_scatter<<<(E1 + 255) / 256, 256>>>(e_src1, e_dst1, cur1, srcs1, E1);

    // 2) layer 0: neighbor mean (double-indirect gather) + fused GEMM + relu
    k_aggregate<true><<<(N1 * 32 + 255) / 256, 256>>>(node_features, input_nodes,
                                                      srcs0, off0, hn0, N1);
    k_gemm<true, true><<<148, 256, smem_bytes>>>(node_features, input_nodes, hn0,
                                                 Ws0, Wn0, b0, h1, N1);

    // 3) layer 1: neighbor mean over h1 + final GEMM (no relu)
    k_aggregate<false><<<(N2 * 32 + 255) / 256, 256>>>(h1, nullptr, srcs1, off1, hn1, N2);
    k_gemm<false, false><<<128, 256, smem_bytes>>>(h1, nullptr, hn1,
                                                   Ws1, Wn1, b1, h2, N2);

    // 4) pos/neg output gathers
    k_out<<<(4 * PP * 32 + 255) / 256, 256>>>(pos_s, pos_d, neg_s, neg_d, out);
}

// round 6
// speedup vs baseline: 1.2697x; 1.2697x over previous
#include <cuda_runtime.h>
#include <cuda_bf16.h>
#include <cstdint>

// Problem constants (fixed by the reference).
#define N_TOTAL 1000000
#define N0      495616
#define N1      45056
#define N2      4096
#define E0      450560
#define E1      40960
#define D       128
#define PP      4096

// ---------------- helpers ----------------
__device__ __forceinline__ uint32_t smem_u32(const void* p) {
    uint32_t a;
    asm("{ .reg .u64 t; cvta.to.shared.u64 t, %1; cvt.u32.u64 %0, t; }" : "=r"(a) : "l"(p));
    return a;
}

__device__ __forceinline__ void ldsm_x4(uint32_t r[4], uint32_t addr) {
    asm volatile("ldmatrix.sync.aligned.m8n8.x4.shared.b16 {%0,%1,%2,%3}, [%4];"
        : "=r"(r[0]), "=r"(r[1]), "=r"(r[2]), "=r"(r[3]) : "r"(addr));
}

// D += A(16x16,row) * B(16x8,col), bf16 in, fp32 acc
__device__ __forceinline__ void mma16816(float d[4], const uint32_t a[4],
                                         uint32_t b0, uint32_t b1) {
    asm volatile("mma.sync.aligned.m16n8k16.row.col.f32.bf16.bf16.f32 "
        "{%0,%1,%2,%3}, {%4,%5,%6,%7}, {%8,%9}, {%0,%1,%2,%3};"
        : "+f"(d[0]), "+f"(d[1]), "+f"(d[2]), "+f"(d[3])
        : "r"(a[0]), "r"(a[1]), "r"(a[2]), "r"(a[3]), "r"(b0), "r"(b1));
}

__device__ __forceinline__ __nv_bfloat16 bf_hi(float v) { return __float2bfloat16(v); }
__device__ __forceinline__ __nv_bfloat16 bf_lo(float v, __nv_bfloat16 h) {
    return __float2bfloat16(v - __bfloat162float(h));
}

// ---------------- device scratch (static, no runtime allocation) ----------------
__device__ float g_hn0[(size_t)N1 * D];
__device__ float g_h1 [(size_t)N1 * D];
__device__ float g_hn1[(size_t)N2 * D];
__device__ float g_h2 [(size_t)N2 * D];

__device__ int g_deg0[N1];
__device__ int g_off0[N1];
__device__ int g_cur0[N1];
__device__ int g_srcs0[E0];

__device__ int g_deg1[N2];
__device__ int g_off1[N2];
__device__ int g_cur1[N2];
__device__ int g_srcs1[E1];

__device__ int g_alloc0;
__device__ int g_alloc1;

// ---------------- CSR build (scan-free) ----------------

__global__ void k_zero() {
    int i = blockIdx.x * blockDim.x + threadIdx.x;
    if (i < N1) g_deg0[i] = 0;
    if (i < N2) g_deg1[i] = 0;
    if (i == 0) { g_alloc0 = 0; g_alloc1 = 0; }
}

__global__ void k_count(const int* __restrict__ d0, const int* __restrict__ d1) {
    int i = blockIdx.x * blockDim.x + threadIdx.x;
    if (i < E0) atomicAdd(&g_deg0[d0[i]], 1);
    if (i < E1) atomicAdd(&g_deg1[d1[i]], 1);
}

// warp-aggregated range allocation: start[d] = atomicAdd(ctr, warp_total) + prefix.
// CSR only needs disjoint regions; global ordering is irrelevant.
__device__ __forceinline__ void alloc_ranges(const int* __restrict__ deg, int* __restrict__ off,
                                             int* __restrict__ cur, int* alloc,
                                             int i, int n, int lane) {
    int d = (i < n) ? deg[i] : 0;
    int x = d;
    #pragma unroll
    for (int o = 1; o < 32; o <<= 1) {
        int t = __shfl_up_sync(0xffffffffu, x, o);
        if (lane >= o) x += t;
    }
    int total = __shfl_sync(0xffffffffu, x, 31);
    int base = 0;
    if (lane == 0 && total > 0) base = atomicAdd(alloc, total);
    base = __shfl_sync(0xffffffffu, base, 0);
    if (i < n) { int s = base + x - d; off[i] = s; cur[i] = s; }
}

__global__ void k_offsets() {
    int i = blockIdx.x * blockDim.x + threadIdx.x;
    int lane = threadIdx.x & 31;
    alloc_ranges(g_deg0, g_off0, g_cur0, &g_alloc0, i, N1, lane);
    alloc_ranges(g_deg1, g_off1, g_cur1, &g_alloc1, i, N2, lane);
}

__global__ void k_scatter(const int* __restrict__ esrc, const int* __restrict__ edst,
                          int* __restrict__ cur, int* __restrict__ srcs, int E) {
    int e = blockIdx.x * blockDim.x + threadIdx.x;
    if (e < E) {
        int d = edst[e];
        int p = atomicAdd(&cur[d], 1);
        srcs[p] = esrc[e];
    }
}

// ---------------- neighbor-mean aggregation: one warp per dst ----------------

template <bool GATHER>
__global__ void k_aggregate(const float* __restrict__ feat, const int* __restrict__ nmap,
                            const int* __restrict__ srcs, const int* __restrict__ off,
                            const int* __restrict__ deg, float* __restrict__ outm, int ndst) {
    int w = (blockIdx.x * blockDim.x + threadIdx.x) >> 5;
    int lane = threadIdx.x & 31;
    if (w >= ndst) return;
    int s = off[w];
    int dg = deg[w];
    int e = s + dg;
    float4 acc = make_float4(0.f, 0.f, 0.f, 0.f);

    int nid_next = 0;
    if (s < e) {
        int src = __ldg(&srcs[s]);
        nid_next = GATHER ? __ldg(&nmap[src]) : src;
    }
    for (int t = s; t < e; t++) {
        int nid = nid_next;
        if (t + 1 < e) {
            int src = __ldg(&srcs[t + 1]);
            nid_next = GATHER ? __ldg(&nmap[src]) : src;
        }
        float4 v = ((const float4*)(feat + (size_t)nid * D))[lane];
        acc.x += v.x; acc.y += v.y; acc.z += v.z; acc.w += v.w;
    }
    float inv = 1.0f / fmaxf((float)dg, 1.0f);
    float4 o = make_float4(acc.x * inv, acc.y * inv, acc.z * inv, acc.w * inv);
    ((float4*)(outm + (size_t)w * D))[lane] = o;
}

// ---------------- tensor-core fused SAGE GEMM (mma.sync bf16, hi/lo split) ----
// out[128-row tile, 0:128] = relu?( hd @ Ws + hn @ Wn + b )
// fp32 -> bf16 hi+lo; C = Ahi*Bhi + Ahi*Blo + Alo*Bhi (fp32 accumulators).
// smem slabs: [128 rows][pitch 136] bf16 (272B rows -> conflict-free ldmatrix).
//   slab0: A_hi   slab1: A_lo
//   slab2: Ws_hi  slab3: Ws_lo   (B layout [n][k], k contiguous)
//   slab4: Wn_hi  slab5: Wn_lo

#define PITCH   136
#define SLABE   (128 * PITCH)          // elements per slab
#define SLAB_B  (SLABE * 2)            // 34816 bytes
#define SMEM_MM (6 * SLAB_B)           // 208896 bytes

template <bool RELU, bool GATHER>
__global__ void __launch_bounds__(256, 1)
k_gemm_mma(const float* __restrict__ hsrc, const int* __restrict__ gidx,
           const float* __restrict__ hnei,
           const float* __restrict__ Ws, const float* __restrict__ Wn,
           const float* __restrict__ bias, float* __restrict__ out, int nrows) {
    extern __shared__ char smem_raw[];
    __nv_bfloat16* slab = (__nv_bfloat16*)smem_raw;
    const uint32_t sb = smem_u32(smem_raw);
    const int tid = threadIdx.x, lane = tid & 31, wid = tid >> 5;

    // ---- stage weights once per CTA: sW[n][k] hi/lo for Ws and Wn ----
    for (int i = tid; i < 16384; i += 256) {
        int k = i >> 7, n = i & 127;
        float w0 = __ldg(&Ws[i]);          // Ws[k][n], coalesced on n
        float w1 = __ldg(&Wn[i]);
        __nv_bfloat16 h0 = bf_hi(w0), l0 = bf_lo(w0, h0);
        __nv_bfloat16 h1 = bf_hi(w1), l1 = bf_lo(w1, h1);
        int o = n * PITCH + k;
        slab[2 * SLABE + o] = h0;
        slab[3 * SLABE + o] = l0;
        slab[4 * SLABE + o] = h1;
        slab[5 * SLABE + o] = l1;
    }

    // staging assignment: 2 threads per row, 64 cols each
    const int r = tid >> 1, c0 = (tid & 1) * 64;

    // ldmatrix address components
    const uint32_t a_row  = (uint32_t)(wid * 16 + (lane & 15));
    const uint32_t a_colq = (uint32_t)((lane >> 4) * 8);
    const uint32_t b_row  = (uint32_t)((lane & 7) + ((lane >> 4) << 3));
    const uint32_t b_col  = (uint32_t)(((lane >> 3) & 1) * 8);

    const int ntiles = nrows / 128;      // nrows is a multiple of 128
    for (int tile = blockIdx.x; tile < ntiles; tile += gridDim.x) {
        const int base = tile * 128;
        float acc[16][4];
        #pragma unroll
        for (int t = 0; t < 16; t++) {
            acc[t][0] = 0.f; acc[t][1] = 0.f; acc[t][2] = 0.f; acc[t][3] = 0.f;
        }

        #pragma unroll
        for (int half = 0; half < 2; half++) {
            __syncthreads();   // prior reads of A slabs (and W staging) complete
            // ---- stage A tile: fp32 -> bf16 hi/lo ----
            const float* src;
            if (half == 0) {
                if (GATHER) {
                    int nid = __ldg(&gidx[base + r]);
                    src = hsrc + (size_t)nid * D + c0;
                } else {
                    src = hsrc + (size_t)(base + r) * D + c0;
                }
            } else {
                src = hnei + (size_t)(base + r) * D + c0;
            }
            #pragma unroll
            for (int i = 0; i < 16; i++) {
                float4 v = ((const float4*)src)[i];
                __nv_bfloat16 hx = bf_hi(v.x), hy = bf_hi(v.y), hz = bf_hi(v.z), hw = bf_hi(v.w);
                __nv_bfloat16 lx = bf_lo(v.x, hx), ly = bf_lo(v.y, hy);
                __nv_bfloat16 lz = bf_lo(v.z, hz), lw = bf_lo(v.w, hw);
                int o = r * PITCH + c0 + 4 * i;
                __nv_bfloat162 h01; h01.x = hx; h01.y = hy;
                __nv_bfloat162 h23; h23.x = hz; h23.y = hw;
                __nv_bfloat162 l01; l01.x = lx; l01.y = ly;
                __nv_bfloat162 l23; l23.x = lz; l23.y = lw;
                uint2 hv; hv.x = *(uint32_t*)&h01; hv.y = *(uint32_t*)&h23;
                uint2 lv; lv.x = *(uint32_t*)&l01; lv.y = *(uint32_t*)&l23;
                *(uint2*)((char*)smem_raw + (size_t)o * 2)          = hv;
                *(uint2*)((char*)smem_raw + SLAB_B + (size_t)o * 2) = lv;
            }
            __syncthreads();

            const uint32_t wHi = sb + (uint32_t)(2 + 2 * half) * SLAB_B;
            const uint32_t wLo = sb + (uint32_t)(3 + 2 * half) * SLAB_B;
            #pragma unroll
            for (int kc = 0; kc < 8; kc++) {
                uint32_t aoff = (a_row * PITCH + (uint32_t)kc * 16 + a_colq) * 2;
                uint32_t aH[4], aL[4];
                ldsm_x4(aH, sb + aoff);
                ldsm_x4(aL, sb + SLAB_B + aoff);
                #pragma unroll
                for (int np = 0; np < 8; np++) {
                    uint32_t boff = (((uint32_t)np * 16 + b_row) * PITCH
                                     + (uint32_t)kc * 16 + b_col) * 2;
                    uint32_t bH[4], bL[4];
                    ldsm_x4(bH, wHi + boff);
                    ldsm_x4(bL, wLo + boff);
                    mma16816(acc[2 * np],     aH, bH[0], bH[1]);
                    mma16816(acc[2 * np],     aH, bL[0], bL[1]);
                    mma16816(acc[2 * np],     aL, bH[0], bH[1]);
                    mma16816(acc[2 * np + 1], aH, bH[2], bH[3]);
                    mma16816(acc[2 * np + 1], aH, bL[2], bL[3]);
                    mma16816(acc[2 * np + 1], aL, bH[2], bH[3]);
                }
            }
        }

        // ---- epilogue: bias (+relu), direct global stores ----
        const int g = lane >> 2, tc = lane & 3;
        const int row0 = base + wid * 16 + g;
        #pragma unroll
        for (int nt = 0; nt < 16; nt++) {
            int n0 = nt * 8 + 2 * tc;
            float2 bv = __ldg((const float2*)(bias + n0));
            float2 v0, v1;
            v0.x = acc[nt][0] + bv.x; v0.y = acc[nt][1] + bv.y;
            v1.x = acc[nt][2] + bv.x; v1.y = acc[nt][3] + bv.y;
            if (RELU) {
                v0.x = fmaxf(v0.x, 0.f); v0.y = fmaxf(v0.y, 0.f);
                v1.x = fmaxf(v1.x, 0.f); v1.y = fmaxf(v1.y, 0.f);
            }
            *(float2*)(out + (size_t)row0 * D + n0)       = v0;
            *(float2*)(out + (size_t)(row0 + 8) * D + n0) = v1;
        }
    }
}

// ---------------- final pos/neg gathers ----------------

__global__ void k_out(const int* __restrict__ ps, const int* __restrict__ pd,
                      const int* __restrict__ ns, const int* __restrict__ nd,
                      float* __restrict__ out) {
    int i = blockIdx.x * blockDim.x + threadIdx.x;
    if (i >= 4 * PP * 32) return;
    int q = i & 31;
    int row = i >> 5;
    int sec = row >> 12;
    int p = row & (PP - 1);
    const int* idx = (sec == 0) ? ps : (sec == 1) ? pd : (sec == 2) ? ns : nd;
    int h = __ldg(&idx[p]);
    ((float4*)out)[i] = ((const float4*)g_h2)[(size_t)h * 32 + q];
}

// ---------------- host launcher ----------------

extern "C" void kernel_launch(void* const* d_in, const int* in_sizes, int n_in,
                              void* d_out, int out_size) {
    const float* node_features = (const float*)d_in[0];
    const int*   input_nodes   = (const int*)d_in[1];
    const int*   e_src0        = (const int*)d_in[2];
    const int*   e_dst0        = (const int*)d_in[3];
    const int*   e_src1        = (const int*)d_in[4];
    const int*   e_dst1        = (const int*)d_in[5];
    const int*   pos_s         = (const int*)d_in[6];
    const int*   pos_d         = (const int*)d_in[7];
    const int*   neg_s         = (const int*)d_in[8];
    const int*   neg_d         = (const int*)d_in[9];
    const float* Ws0           = (const float*)d_in[10];
    const float* Wn0           = (const float*)d_in[11];
    const float* b0            = (const float*)d_in[12];
    const float* Ws1           = (const float*)d_in[13];
    const float* Wn1           = (const float*)d_in[14];
    const float* b1            = (const float*)d_in[15];
    float* out = (float*)d_out;

    void *p_hn0, *p_h1, *p_hn1, *p_h2;
    void *p_deg0, *p_off0, *p_cur0, *p_srcs0;
    void *p_deg1, *p_off1, *p_cur1, *p_srcs1;
    cudaGetSymbolAddress(&p_hn0, g_hn0);
    cudaGetSymbolAddress(&p_h1,  g_h1);
    cudaGetSymbolAddress(&p_hn1, g_hn1);
    cudaGetSymbolAddress(&p_h2,  g_h2);
    cudaGetSymbolAddress(&p_deg0, g_deg0);
    cudaGetSymbolAddress(&p_off0, g_off0);
    cudaGetSymbolAddress(&p_cur0, g_cur0);
    cudaGetSymbolAddress(&p_srcs0, g_srcs0);
    cudaGetSymbolAddress(&p_deg1, g_deg1);
    cudaGetSymbolAddress(&p_off1, g_off1);
    cudaGetSymbolAddress(&p_cur1, g_cur1);
    cudaGetSymbolAddress(&p_srcs1, g_srcs1);

    float* hn0 = (float*)p_hn0;  float* h1 = (float*)p_h1;
    float* hn1 = (float*)p_hn1;  float* h2 = (float*)p_h2;
    int* off0 = (int*)p_off0; int* cur0 = (int*)p_cur0; int* srcs0 = (int*)p_srcs0;
    int* deg0 = (int*)p_deg0;
    int* off1 = (int*)p_off1; int* cur1 = (int*)p_cur1; int* srcs1 = (int*)p_srcs1;
    int* deg1 = (int*)p_deg1;

    cudaFuncSetAttribute((const void*)k_gemm_mma<true, true>,
                         cudaFuncAttributeMaxDynamicSharedMemorySize, SMEM_MM);
    cudaFuncSetAttribute((const void*)k_gemm_mma<false, false>,
                         cudaFuncAttributeMaxDynamicSharedMemorySize, SMEM_MM);

    // 1) CSR build (scan-free: warp-aggregated range allocation)
    k_zero<<<(N1 + 255) / 256, 256>>>();
    k_count<<<(E0 + 255) / 256, 256>>>(e_dst0, e_dst1);
    k_offsets<<<(N1 + 255) / 256, 256>>>();
    k_scatter<<<(E0 + 255) / 256, 256>>>(e_src0, e_dst0, cur0, srcs0, E0);
    k_scatter<<<(E1 + 255) / 256, 256>>>(e_src1, e_dst1, cur1, srcs1, E1);

    // 2) layer 0: neighbor mean + tensor-core fused GEMM + relu
    k_aggregate<true><<<(N1 * 32 + 255) / 256, 256>>>(node_features, input_nodes,
                                                      srcs0, off0, deg0, hn0, N1);
    k_gemm_mma<true, true><<<148, 256, SMEM_MM>>>(node_features, input_nodes, hn0,
                                                  Ws0, Wn0, b0, h1, N1);

    // 3) layer 1: neighbor mean over h1 + final GEMM (no relu)
    k_aggregate<false><<<(N2 * 32 + 255) / 256, 256>>>(h1, nullptr, srcs1, off1, deg1, hn1, N2);
    k_gemm_mma<false, false><<<32, 256, SMEM_MM>>>(h1, nullptr, hn1,
                                                   Ws1, Wn1, b1, h2, N2);

    // 4) pos/neg output gathers
    k_out<<<(4 * PP * 32 + 255) / 256, 256>>>(pos_s, pos_d, neg_s, neg_d, out);
}